// round 13
// baseline (speedup 1.0000x reference)
#include <cuda_runtime.h>

#ifndef M_PI_F
#define M_PI_F 3.14159265358979323846f
#endif

#define FDIM 512
#define NOUT 100
#define RB   8             // rows per task
#define WPB  4             // warps per block (128 threads)
#define STAGES 5           // 5-slot ring: prefetch distance 4 rows
#define GRID_BLOCKS 740    // 148 SMs x 5 blocks: one balanced wave

__device__ __forceinline__ void cp_async16(unsigned int saddr, const void* gaddr) {
    asm volatile("cp.async.cg.shared.global [%0], [%1], 16;" :: "r"(saddr), "l"(gaddr));
}
__device__ __forceinline__ void cp_commit() {
    asm volatile("cp.async.commit_group;" ::: "memory");
}
template <int N>
__device__ __forceinline__ void cp_wait() {
    asm volatile("cp.async.wait_group %0;" :: "n"(N) : "memory");
}
__device__ __forceinline__ unsigned long long ffma2(unsigned long long a,
                                                    unsigned long long b,
                                                    unsigned long long c) {
    unsigned long long d;
    asm("fma.rn.f32x2 %0, %1, %2, %3;" : "=l"(d) : "l"(a), "l"(b), "l"(c));
    return d;
}
__device__ __forceinline__ float f32x2_hsum(unsigned long long v) {
    float lo, hi;
    asm("mov.b64 {%0, %1}, %2;" : "=f"(lo), "=f"(hi) : "l"(v));
    return lo + hi;
}
__device__ __forceinline__ float fast_tanh(float x) {
    return 1.0f - 2.0f / (__expf(2.0f * x) + 1.0f);
}

// R12 (persistent warps, continuous cp.async ring) with latency surgery:
//  - NO per-row __syncwarp: each lane consumes exactly the bytes its own
//    cp.async wrote (same lane+32k addressing), wait_group suffices per-lane
//  - 5-slot ring, issue-before-wait, wait_group 4 -> prefetch distance 4 rows
//    (~485cyc) nearly covers the 577cyc DRAM latency (was 3 rows / ~364cyc)
__global__ __launch_bounds__(128, 5)
void qnet_fused_kernel(const float* __restrict__ X,
                       const float* __restrict__ preW,
                       const float* __restrict__ preB,
                       const float* __restrict__ qp,
                       const float* __restrict__ postW,
                       const float* __restrict__ postB,
                       float* __restrict__ out,
                       int B)
{
    __shared__ float4 xring[WPB][STAGES][128];   // 40KB static -> 5 blocks/SM

    const int tid  = threadIdx.x;
    const int wid  = tid >> 5;
    const int lane = tid & 31;

    const int n_tasks     = (B + RB - 1) / RB;
    const int warp_g      = blockIdx.x * WPB + wid;
    const int warp_stride = gridDim.x * WPB;
    if (warp_g >= n_tasks) return;
    const int n_my_tasks = (n_tasks - 1 - warp_g) / warp_stride + 1;

    const float4* __restrict__ X4 = reinterpret_cast<const float4*>(X);

    // i-th row in this warp's sequence -> global row index (clamped)
    auto row_of = [&](int i) -> int {
        const int t = warp_g + (i >> 3) * warp_stride;
        return min(t * RB + (i & 7), B - 1);
    };
    auto issue_slot = [&](int slot, int i) {
        const float4* __restrict__ src = X4 + (size_t)row_of(i) * 128;
        float4* dst = &xring[wid][slot][0];
        #pragma unroll
        for (int k = 0; k < 4; ++k) {
            unsigned int sa = (unsigned int)__cvta_generic_to_shared(dst + lane + 32 * k);
            cp_async16(sa, src + lane + 32 * k);
        }
        cp_commit();
    };

    issue_slot(0, 0); issue_slot(1, 1); issue_slot(2, 2); issue_slot(3, 3);
    int prod_row = 4;    // next warp-sequence row to issue
    int slot_p   = 4;    // its ring slot
    int slot_c   = 0;    // consume slot

    // ---- once-per-warp prolog (overlaps the first loads) ----
    const ulonglong2* __restrict__ Wp = reinterpret_cast<const ulonglong2*>(preW);
    unsigned long long w0p[8], w1p[8], w2p[8];
    #pragma unroll
    for (int k = 0; k < 4; ++k) {
        const int i = lane + 32 * k;
        ulonglong2 q0 = __ldg(Wp + i);
        ulonglong2 q1 = __ldg(Wp + 128 + i);
        ulonglong2 q2 = __ldg(Wp + 256 + i);
        w0p[2 * k] = q0.x; w0p[2 * k + 1] = q0.y;
        w1p[2 * k] = q1.x; w1p[2 * k + 1] = q1.y;
        w2p[2 * k] = q2.x; w2p[2 * k + 1] = q2.y;
    }
    const float pb0 = __ldg(preB + 0), pb1 = __ldg(preB + 1), pb2 = __ldg(preB + 2);
    float qw[6];
    #pragma unroll
    for (int j = 0; j < 6; ++j) qw[j] = __ldg(qp + 3 + j);

    const int grp  = lane >> 3;
    const int mr   = lane & 7;
    const int srcl = (mr & 3) << 3;

    const float4* __restrict__ pW4 = reinterpret_cast<const float4*>(postW);
    const float4* __restrict__ pB4 = reinterpret_cast<const float4*>(postB);

    for (int it = 0; it < n_my_tasks; ++it) {
        const int  task = warp_g + it * warp_stride;
        const int  base = task * RB;
        const bool lastTask = (it == n_my_tasks - 1);

        float c0a = 0.f, c1a = 0.f, c2a = 0.f;
        float c0b = 0.f, c1b = 0.f, c2b = 0.f;

        #pragma unroll
        for (int r = 0; r < RB; ++r) {
            // issue first (deeper prefetch), then wait
            if (!lastTask || r < 4) {
                issue_slot(slot_p, prod_row);
                ++prod_row;
                slot_p = (slot_p == STAGES - 1) ? 0 : slot_p + 1;
            }
            if (!lastTask || r < 4)  cp_wait<4>();
            else if (r == 4)         cp_wait<3>();
            else if (r == 5)         cp_wait<2>();
            else if (r == 6)         cp_wait<1>();
            else                     cp_wait<0>();
            // no __syncwarp: each lane reads only its own cp.async'd bytes

            const ulonglong2* xs = reinterpret_cast<const ulonglong2*>(
                &xring[wid][slot_c][0]);
            slot_c = (slot_c == STAGES - 1) ? 0 : slot_c + 1;

            unsigned long long acc0 = 0, acc1 = 0, acc2 = 0;
            #pragma unroll
            for (int k = 0; k < 4; ++k) {
                const ulonglong2 xv = xs[lane + 32 * k];
                acc0 = ffma2(xv.x, w0p[2 * k],     acc0);
                acc0 = ffma2(xv.y, w0p[2 * k + 1], acc0);
                acc1 = ffma2(xv.x, w1p[2 * k],     acc1);
                acc1 = ffma2(xv.y, w1p[2 * k + 1], acc1);
                acc2 = ffma2(xv.x, w2p[2 * k],     acc2);
                acc2 = ffma2(xv.y, w2p[2 * k + 1], acc2);
            }

            float v0 = f32x2_hsum(acc0);
            float v1 = f32x2_hsum(acc1);
            float v2 = f32x2_hsum(acc2);

            v0 += __shfl_xor_sync(0xFFFFFFFFu, v0, 16);
            v1 += __shfl_xor_sync(0xFFFFFFFFu, v1, 16);
            v2 += __shfl_xor_sync(0xFFFFFFFFu, v2, 16);
            v0 += __shfl_xor_sync(0xFFFFFFFFu, v0, 8);
            v1 += __shfl_xor_sync(0xFFFFFFFFu, v1, 8);
            v2 += __shfl_xor_sync(0xFFFFFFFFu, v2, 8);

            const bool g = (grp == (r & 3));
            if (r < 4) {
                c0a = g ? v0 : c0a;  c1a = g ? v1 : c1a;  c2a = g ? v2 : c2a;
            } else {
                c0b = g ? v0 : c0b;  c1b = g ? v1 : c1b;  c2b = g ? v2 : c2b;
            }
        }

        #pragma unroll
        for (int off = 4; off > 0; off >>= 1) {
            c0a += __shfl_xor_sync(0xFFFFFFFFu, c0a, off);
            c1a += __shfl_xor_sync(0xFFFFFFFFu, c1a, off);
            c2a += __shfl_xor_sync(0xFFFFFFFFu, c2a, off);
            c0b += __shfl_xor_sync(0xFFFFFFFFu, c0b, off);
            c1b += __shfl_xor_sync(0xFFFFFFFFu, c1b, off);
            c2b += __shfl_xor_sync(0xFFFFFFFFu, c2b, off);
        }

        const float xa0 = __shfl_sync(0xFFFFFFFFu, c0a, srcl);
        const float xb0 = __shfl_sync(0xFFFFFFFFu, c0b, srcl);
        const float xa1 = __shfl_sync(0xFFFFFFFFu, c1a, srcl);
        const float xb1 = __shfl_sync(0xFFFFFFFFu, c1b, srcl);
        const float xa2 = __shfl_sync(0xFFFFFFFFu, c2a, srcl);
        const float xb2 = __shfl_sync(0xFFFFFFFFu, c2b, srcl);
        const float a0 = (mr < 4) ? xa0 : xb0;
        const float a1 = (mr < 4) ? xa1 : xb1;
        const float a2 = (mr < 4) ? xa2 : xb2;

        // ---- per-lane circuit ----
        const float t0 = fast_tanh(a0 + pb0) * (M_PI_F * 0.5f);
        const float t1 = fast_tanh(a1 + pb1) * (M_PI_F * 0.5f);
        const float t2 = fast_tanh(a2 + pb2) * (M_PI_F * 0.5f);

        float s[8];
        const float inv_sqrt8 = 0.3535533905932738f;
        #pragma unroll
        for (int i = 0; i < 8; ++i) s[i] = inv_sqrt8;

        auto ry0 = [&](float th) {
            float sn, cs; __sincosf(th * 0.5f, &sn, &cs);
            #pragma unroll
            for (int i = 0; i < 4; ++i) {
                float a = s[i], b = s[i + 4];
                s[i]     = cs * a - sn * b;
                s[i + 4] = sn * a + cs * b;
            }
        };
        auto ry1 = [&](float th) {
            float sn, cs; __sincosf(th * 0.5f, &sn, &cs);
            #pragma unroll
            for (int g2 = 0; g2 < 2; ++g2)
                #pragma unroll
                for (int i = 0; i < 2; ++i) {
                    int lo = g2 * 4 + i;
                    float a = s[lo], b = s[lo + 2];
                    s[lo]     = cs * a - sn * b;
                    s[lo + 2] = sn * a + cs * b;
                }
        };
        auto ry2 = [&](float th) {
            float sn, cs; __sincosf(th * 0.5f, &sn, &cs);
            #pragma unroll
            for (int g2 = 0; g2 < 4; ++g2) {
                int lo = g2 * 2;
                float a = s[lo], b = s[lo + 1];
                s[lo]     = cs * a - sn * b;
                s[lo + 1] = sn * a + cs * b;
            }
        };

        ry0(t0); ry1(t1); ry2(t2);

        #pragma unroll
        for (int k = 0; k < 2; ++k) {
            float tmp;
            tmp = s[4]; s[4] = s[6]; s[6] = tmp;   // CNOT(0,1)
            tmp = s[5]; s[5] = s[7]; s[7] = tmp;
            tmp = s[2]; s[2] = s[3]; s[3] = tmp;   // CNOT(1,2)
            tmp = s[6]; s[6] = s[7]; s[7] = tmp;
            ry0(qw[3 * k + 0]);
            ry1(qw[3 * k + 1]);
            ry2(qw[3 * k + 2]);
        }

        float p[8];
        #pragma unroll
        for (int i = 0; i < 8; ++i) p[i] = s[i] * s[i];

        const float z0 = (p[0] + p[1] + p[2] + p[3]) - (p[4] + p[5] + p[6] + p[7]);
        const float z1 = (p[0] + p[1] + p[4] + p[5]) - (p[2] + p[3] + p[6] + p[7]);
        const float z2 = (p[0] + p[2] + p[4] + p[6]) - (p[1] + p[3] + p[5] + p[7]);

        // ---- epilogue: this task's rows x 25 float4, contiguous ----
        const int rows = min(RB, B - base);
        float4* __restrict__ out4 = reinterpret_cast<float4*>(out) + (size_t)base * 25;
        const int lim = rows * 25;
        #pragma unroll
        for (int i = 0; i < 7; ++i) {
            const int f4  = i * 32 + lane;      // 0..223 ; valid < 200
            const int row = f4 / 25;
            const int g2  = f4 - row * 25;
            const float zz0 = __shfl_sync(0xFFFFFFFFu, z0, row & 7);
            const float zz1 = __shfl_sync(0xFFFFFFFFu, z1, row & 7);
            const float zz2 = __shfl_sync(0xFFFFFFFFu, z2, row & 7);
            if (f4 < lim) {
                const float4 f0 = __ldg(pW4 + 3 * g2 + 0);
                const float4 f1 = __ldg(pW4 + 3 * g2 + 1);
                const float4 f2 = __ldg(pW4 + 3 * g2 + 2);
                const float4 bb = __ldg(pB4 + g2);
                float4 o;
                o.x = zz0 * f0.x + zz1 * f0.y + zz2 * f0.z + bb.x;
                o.y = zz0 * f0.w + zz1 * f1.x + zz2 * f1.y + bb.y;
                o.z = zz0 * f1.z + zz1 * f1.w + zz2 * f2.x + bb.z;
                o.w = zz0 * f2.y + zz1 * f2.z + zz2 * f2.w + bb.w;
                __stcs(out4 + f4, o);
            }
        }
    }
}

extern "C" void kernel_launch(void* const* d_in, const int* in_sizes, int n_in,
                              void* d_out, int out_size)
{
    const float* X     = (const float*)d_in[0]; // [B, 512]
    const float* preW  = (const float*)d_in[1]; // [3, 512]
    const float* preB  = (const float*)d_in[2]; // [3]
    const float* qp    = (const float*)d_in[3]; // [45]
    const float* postW = (const float*)d_in[4]; // [100, 3]
    const float* postB = (const float*)d_in[5]; // [100]
    float* out = (float*)d_out;                 // [B, 100]

    const int B = in_sizes[0] / FDIM;
    const int n_tasks = (B + RB - 1) / RB;
    int blocks = (n_tasks + WPB - 1) / WPB;
    if (blocks > GRID_BLOCKS) blocks = GRID_BLOCKS;

    qnet_fused_kernel<<<blocks, WPB * 32>>>(X, preW, preB, qp, postW, postB, out, B);
}

// round 14
// speedup vs baseline: 1.0439x; 1.0439x over previous
#include <cuda_runtime.h>

#ifndef M_PI_F
#define M_PI_F 3.14159265358979323846f
#endif

#define FDIM 512
#define NOUT 100
#define RB   8             // rows per task
#define WPB  4             // warps per block (128 threads)
#define STAGES 4
#define GRID_BLOCKS 740    // 148 SMs x 5 blocks: one perfectly balanced wave

__device__ __forceinline__ void cp_async16(unsigned int saddr, const void* gaddr) {
    asm volatile("cp.async.cg.shared.global [%0], [%1], 16;" :: "r"(saddr), "l"(gaddr));
}
__device__ __forceinline__ void cp_commit() {
    asm volatile("cp.async.commit_group;" ::: "memory");
}
template <int N>
__device__ __forceinline__ void cp_wait() {
    asm volatile("cp.async.wait_group %0;" :: "n"(N) : "memory");
}
__device__ __forceinline__ unsigned long long ffma2(unsigned long long a,
                                                    unsigned long long b,
                                                    unsigned long long c) {
    unsigned long long d;
    asm("fma.rn.f32x2 %0, %1, %2, %3;" : "=l"(d) : "l"(a), "l"(b), "l"(c));
    return d;
}
__device__ __forceinline__ float f32x2_hsum(unsigned long long v) {
    float lo, hi;
    asm("mov.b64 {%0, %1}, %2;" : "=f"(lo), "=f"(hi) : "l"(v));
    return lo + hi;
}
__device__ __forceinline__ float fast_tanh(float x) {
    return 1.0f - 2.0f / (__expf(2.0f * x) + 1.0f);
}

// R12 (best: 33.3us) with exactly ONE delta: the per-row __syncwarp removed.
// Safe because each lane consumes exactly the bytes its own cp.async wrote
// (dst[lane+32k] == xs[lane+32k]) and wait_group orders a thread's own copies.
// Ring addressing stays compile-time (i & 3 == r & 3 since tasks stride 8).
__global__ __launch_bounds__(128, 5)
void qnet_fused_kernel(const float* __restrict__ X,
                       const float* __restrict__ preW,
                       const float* __restrict__ preB,
                       const float* __restrict__ qp,
                       const float* __restrict__ postW,
                       const float* __restrict__ postB,
                       float* __restrict__ out,
                       int B)
{
    __shared__ float4 xring[WPB][STAGES][128];   // 32KB static

    const int tid  = threadIdx.x;
    const int wid  = tid >> 5;
    const int lane = tid & 31;

    const int n_tasks     = (B + RB - 1) / RB;
    const int warp_g      = blockIdx.x * WPB + wid;
    const int warp_stride = gridDim.x * WPB;
    if (warp_g >= n_tasks) return;
    const int n_my_tasks = (n_tasks - 1 - warp_g) / warp_stride + 1;

    const float4* __restrict__ X4 = reinterpret_cast<const float4*>(X);

    // i-th row in this warp's sequence -> global row index (clamped)
    auto row_of = [&](int i) -> int {
        const int t = warp_g + (i >> 3) * warp_stride;
        return min(t * RB + (i & 7), B - 1);
    };
    auto issue = [&](int i) {
        const float4* __restrict__ src = X4 + (size_t)row_of(i) * 128;
        float4* dst = &xring[wid][i & (STAGES - 1)][0];
        #pragma unroll
        for (int k = 0; k < 4; ++k) {
            unsigned int sa = (unsigned int)__cvta_generic_to_shared(dst + lane + 32 * k);
            cp_async16(sa, src + lane + 32 * k);
        }
        cp_commit();
    };

    issue(0); issue(1); issue(2); issue(3);

    // ---- once-per-warp prolog (overlaps the first loads) ----
    const ulonglong2* __restrict__ Wp = reinterpret_cast<const ulonglong2*>(preW);
    unsigned long long w0p[8], w1p[8], w2p[8];
    #pragma unroll
    for (int k = 0; k < 4; ++k) {
        const int i = lane + 32 * k;
        ulonglong2 q0 = __ldg(Wp + i);
        ulonglong2 q1 = __ldg(Wp + 128 + i);
        ulonglong2 q2 = __ldg(Wp + 256 + i);
        w0p[2 * k] = q0.x; w0p[2 * k + 1] = q0.y;
        w1p[2 * k] = q1.x; w1p[2 * k + 1] = q1.y;
        w2p[2 * k] = q2.x; w2p[2 * k + 1] = q2.y;
    }
    const float pb0 = __ldg(preB + 0), pb1 = __ldg(preB + 1), pb2 = __ldg(preB + 2);
    float qw[6];
    #pragma unroll
    for (int j = 0; j < 6; ++j) qw[j] = __ldg(qp + 3 + j);

    const int grp  = lane >> 3;
    const int mr   = lane & 7;
    const int srcl = (mr & 3) << 3;

    const float4* __restrict__ pW4 = reinterpret_cast<const float4*>(postW);
    const float4* __restrict__ pB4 = reinterpret_cast<const float4*>(postB);

    for (int it = 0; it < n_my_tasks; ++it) {
        const int  task = warp_g + it * warp_stride;
        const int  base = task * RB;
        const bool lastTask = (it == n_my_tasks - 1);

        float c0a = 0.f, c1a = 0.f, c2a = 0.f;
        float c0b = 0.f, c1b = 0.f, c2b = 0.f;

        #pragma unroll
        for (int r = 0; r < RB; ++r) {
            const int i = it * RB + r;
            if (!lastTask || r < 5)  cp_wait<3>();
            else if (r == 5)         cp_wait<2>();
            else if (r == 6)         cp_wait<1>();
            else                     cp_wait<0>();
            // no __syncwarp: each lane reads only its own cp.async'd bytes

            const ulonglong2* xs = reinterpret_cast<const ulonglong2*>(
                &xring[wid][i & (STAGES - 1)][0]);
            unsigned long long acc0 = 0, acc1 = 0, acc2 = 0;
            #pragma unroll
            for (int k = 0; k < 4; ++k) {
                const ulonglong2 xv = xs[lane + 32 * k];
                acc0 = ffma2(xv.x, w0p[2 * k],     acc0);
                acc0 = ffma2(xv.y, w0p[2 * k + 1], acc0);
                acc1 = ffma2(xv.x, w1p[2 * k],     acc1);
                acc1 = ffma2(xv.y, w1p[2 * k + 1], acc1);
                acc2 = ffma2(xv.x, w2p[2 * k],     acc2);
                acc2 = ffma2(xv.y, w2p[2 * k + 1], acc2);
            }
            if (!lastTask || r < 4) issue(i + 4);   // continuous across tasks

            float v0 = f32x2_hsum(acc0);
            float v1 = f32x2_hsum(acc1);
            float v2 = f32x2_hsum(acc2);

            v0 += __shfl_xor_sync(0xFFFFFFFFu, v0, 16);
            v1 += __shfl_xor_sync(0xFFFFFFFFu, v1, 16);
            v2 += __shfl_xor_sync(0xFFFFFFFFu, v2, 16);
            v0 += __shfl_xor_sync(0xFFFFFFFFu, v0, 8);
            v1 += __shfl_xor_sync(0xFFFFFFFFu, v1, 8);
            v2 += __shfl_xor_sync(0xFFFFFFFFu, v2, 8);

            const bool g = (grp == (r & 3));
            if (r < 4) {
                c0a = g ? v0 : c0a;  c1a = g ? v1 : c1a;  c2a = g ? v2 : c2a;
            } else {
                c0b = g ? v0 : c0b;  c1b = g ? v1 : c1b;  c2b = g ? v2 : c2b;
            }
        }

        #pragma unroll
        for (int off = 4; off > 0; off >>= 1) {
            c0a += __shfl_xor_sync(0xFFFFFFFFu, c0a, off);
            c1a += __shfl_xor_sync(0xFFFFFFFFu, c1a, off);
            c2a += __shfl_xor_sync(0xFFFFFFFFu, c2a, off);
            c0b += __shfl_xor_sync(0xFFFFFFFFu, c0b, off);
            c1b += __shfl_xor_sync(0xFFFFFFFFu, c1b, off);
            c2b += __shfl_xor_sync(0xFFFFFFFFu, c2b, off);
        }

        const float xa0 = __shfl_sync(0xFFFFFFFFu, c0a, srcl);
        const float xb0 = __shfl_sync(0xFFFFFFFFu, c0b, srcl);
        const float xa1 = __shfl_sync(0xFFFFFFFFu, c1a, srcl);
        const float xb1 = __shfl_sync(0xFFFFFFFFu, c1b, srcl);
        const float xa2 = __shfl_sync(0xFFFFFFFFu, c2a, srcl);
        const float xb2 = __shfl_sync(0xFFFFFFFFu, c2b, srcl);
        const float a0 = (mr < 4) ? xa0 : xb0;
        const float a1 = (mr < 4) ? xa1 : xb1;
        const float a2 = (mr < 4) ? xa2 : xb2;

        // ---- per-lane circuit ----
        const float t0 = fast_tanh(a0 + pb0) * (M_PI_F * 0.5f);
        const float t1 = fast_tanh(a1 + pb1) * (M_PI_F * 0.5f);
        const float t2 = fast_tanh(a2 + pb2) * (M_PI_F * 0.5f);

        float s[8];
        const float inv_sqrt8 = 0.3535533905932738f;
        #pragma unroll
        for (int i = 0; i < 8; ++i) s[i] = inv_sqrt8;

        auto ry0 = [&](float th) {
            float sn, cs; __sincosf(th * 0.5f, &sn, &cs);
            #pragma unroll
            for (int i = 0; i < 4; ++i) {
                float a = s[i], b = s[i + 4];
                s[i]     = cs * a - sn * b;
                s[i + 4] = sn * a + cs * b;
            }
        };
        auto ry1 = [&](float th) {
            float sn, cs; __sincosf(th * 0.5f, &sn, &cs);
            #pragma unroll
            for (int g2 = 0; g2 < 2; ++g2)
                #pragma unroll
                for (int i = 0; i < 2; ++i) {
                    int lo = g2 * 4 + i;
                    float a = s[lo], b = s[lo + 2];
                    s[lo]     = cs * a - sn * b;
                    s[lo + 2] = sn * a + cs * b;
                }
        };
        auto ry2 = [&](float th) {
            float sn, cs; __sincosf(th * 0.5f, &sn, &cs);
            #pragma unroll
            for (int g2 = 0; g2 < 4; ++g2) {
                int lo = g2 * 2;
                float a = s[lo], b = s[lo + 1];
                s[lo]     = cs * a - sn * b;
                s[lo + 1] = sn * a + cs * b;
            }
        };

        ry0(t0); ry1(t1); ry2(t2);

        #pragma unroll
        for (int k = 0; k < 2; ++k) {
            float tmp;
            tmp = s[4]; s[4] = s[6]; s[6] = tmp;   // CNOT(0,1)
            tmp = s[5]; s[5] = s[7]; s[7] = tmp;
            tmp = s[2]; s[2] = s[3]; s[3] = tmp;   // CNOT(1,2)
            tmp = s[6]; s[6] = s[7]; s[7] = tmp;
            ry0(qw[3 * k + 0]);
            ry1(qw[3 * k + 1]);
            ry2(qw[3 * k + 2]);
        }

        float p[8];
        #pragma unroll
        for (int i = 0; i < 8; ++i) p[i] = s[i] * s[i];

        const float z0 = (p[0] + p[1] + p[2] + p[3]) - (p[4] + p[5] + p[6] + p[7]);
        const float z1 = (p[0] + p[1] + p[4] + p[5]) - (p[2] + p[3] + p[6] + p[7]);
        const float z2 = (p[0] + p[2] + p[4] + p[6]) - (p[1] + p[3] + p[5] + p[7]);

        // ---- epilogue: this task's rows x 25 float4, contiguous ----
        const int rows = min(RB, B - base);
        float4* __restrict__ out4 = reinterpret_cast<float4*>(out) + (size_t)base * 25;
        const int lim = rows * 25;
        #pragma unroll
        for (int i = 0; i < 7; ++i) {
            const int f4  = i * 32 + lane;      // 0..223 ; valid < 200
            const int row = f4 / 25;
            const int g2  = f4 - row * 25;
            const float zz0 = __shfl_sync(0xFFFFFFFFu, z0, row & 7);
            const float zz1 = __shfl_sync(0xFFFFFFFFu, z1, row & 7);
            const float zz2 = __shfl_sync(0xFFFFFFFFu, z2, row & 7);
            if (f4 < lim) {
                const float4 f0 = __ldg(pW4 + 3 * g2 + 0);
                const float4 f1 = __ldg(pW4 + 3 * g2 + 1);
                const float4 f2 = __ldg(pW4 + 3 * g2 + 2);
                const float4 bb = __ldg(pB4 + g2);
                float4 o;
                o.x = zz0 * f0.x + zz1 * f0.y + zz2 * f0.z + bb.x;
                o.y = zz0 * f0.w + zz1 * f1.x + zz2 * f1.y + bb.y;
                o.z = zz0 * f1.z + zz1 * f1.w + zz2 * f2.x + bb.z;
                o.w = zz0 * f2.y + zz1 * f2.z + zz2 * f2.w + bb.w;
                __stcs(out4 + f4, o);
            }
        }
    }
}

extern "C" void kernel_launch(void* const* d_in, const int* in_sizes, int n_in,
                              void* d_out, int out_size)
{
    const float* X     = (const float*)d_in[0]; // [B, 512]
    const float* preW  = (const float*)d_in[1]; // [3, 512]
    const float* preB  = (const float*)d_in[2]; // [3]
    const float* qp    = (const float*)d_in[3]; // [45]
    const float* postW = (const float*)d_in[4]; // [100, 3]
    const float* postB = (const float*)d_in[5]; // [100]
    float* out = (float*)d_out;                 // [B, 100]

    const int B = in_sizes[0] / FDIM;
    const int n_tasks = (B + RB - 1) / RB;
    int blocks = (n_tasks + WPB - 1) / WPB;
    if (blocks > GRID_BLOCKS) blocks = GRID_BLOCKS;

    qnet_fused_kernel<<<blocks, WPB * 32>>>(X, preW, preB, qp, postW, postB, out, B);
}